// round 15
// baseline (speedup 1.0000x reference)
#include <cuda_runtime.h>
#include <cuda_bf16.h>
#include <math.h>
#include <stdint.h>

#define BB 8
#define SS 2048
#define DD 1024
#define HH 16
#define DHH 64
#define M_TOT (BB*SS)

// ---------------------------------------------------------------------------
// Device scratch (allocation-free rule)
// ---------------------------------------------------------------------------
__device__ float g_q[(size_t)M_TOT * DD];            // fp32 q (pool/residual)
__device__ float g_k[(size_t)M_TOT * DD];
__device__ float g_qa[(size_t)M_TOT * HH];           // [row][h]
__device__ float g_pq[BB * DD];
__device__ float g_pk[BB * DD];
__device__ float g_wqa2[DD * HH];                    // Wq @ Wqa  [k][h]
__device__ float g_bias2[HH];                        // bq @ Wqa + bqa
__device__ __nv_bfloat16 g_ah[(size_t)M_TOT * DD];   // split(hs)
__device__ __nv_bfloat16 g_al[(size_t)M_TOT * DD];
__device__ __nv_bfloat16 g_qh[(size_t)M_TOT * DD];   // split(q), from gemm1 epilogue
__device__ __nv_bfloat16 g_ql[(size_t)M_TOT * DD];
__device__ __nv_bfloat16 g_wh1[DD * DD];             // Wq^T (N-major, K contiguous)
__device__ __nv_bfloat16 g_wl1[DD * DD];
__device__ __nv_bfloat16 g_wh2[DD * DD];             // Wk^T
__device__ __nv_bfloat16 g_wl2[DD * DD];
__device__ __nv_bfloat16 g_wth8[(size_t)BB * DD * DD]; // per-batch (diag(pk[b])*Wt)^T hi
__device__ __nv_bfloat16 g_wtl8[(size_t)BB * DD * DD]; // lo

// ---------------------------------------------------------------------------
// PTX helpers (sm_103-safe: mma.sync / ldmatrix / cp.async only)
// ---------------------------------------------------------------------------
__device__ __forceinline__ uint32_t smem_to_u32(const void* p) {
    uint32_t a;
    asm("{ .reg .u64 t; cvta.to.shared.u64 t, %1; cvt.u32.u64 %0, t; }" : "=r"(a) : "l"(p));
    return a;
}
__device__ __forceinline__ void cp16(uint32_t s, const void* g) {
    asm volatile("cp.async.cg.shared.global [%0], [%1], 16;" :: "r"(s), "l"(g));
}
#define CP_COMMIT() asm volatile("cp.async.commit_group;" ::: "memory")
#define CP_WAIT(n)  asm volatile("cp.async.wait_group %0;" :: "n"(n) : "memory")

__device__ __forceinline__ void ldsm4(uint32_t* r, uint32_t a) {
    asm volatile("ldmatrix.sync.aligned.m8n8.x4.shared.b16 {%0,%1,%2,%3}, [%4];"
                 : "=r"(r[0]), "=r"(r[1]), "=r"(r[2]), "=r"(r[3]) : "r"(a));
}
__device__ __forceinline__ void mma16816(float* c, const uint32_t* a, const uint32_t* b) {
    asm volatile("mma.sync.aligned.m16n8k16.row.col.f32.bf16.bf16.f32 "
                 "{%0,%1,%2,%3}, {%4,%5,%6,%7}, {%8,%9}, {%0,%1,%2,%3};"
                 : "+f"(c[0]), "+f"(c[1]), "+f"(c[2]), "+f"(c[3])
                 : "r"(a[0]), "r"(a[1]), "r"(a[2]), "r"(a[3]), "r"(b[0]), "r"(b[1]));
}
__device__ __forceinline__ void split1(float x, __nv_bfloat16& h, __nv_bfloat16& l) {
    h = __float2bfloat16(x);
    l = __float2bfloat16(x - __bfloat162float(h));
}

// ---------------------------------------------------------------------------
// bf16x3 GEMM via mma.sync (best config: 128x128 CTA tile, BK=32, 256 thr,
// 8 warps 2x4 -> warp tile 64x32, 3-stage cp.async ring, one sync per K-step).
// ---------------------------------------------------------------------------
#define BKT 32
#define NKT2 (DD / BKT)          // 32
#define ARR_BYTES 8192           // 128 rows x 64B
#define STAGE_BYTES (4 * ARR_BYTES)
#define NST 3
#define GEMM_SMEM (NST * STAGE_BYTES + 128)

__device__ __forceinline__ uint32_t sw_off(int row, int chunk) {
    return (uint32_t)(row * 64 + ((chunk ^ ((row >> 1) & 3)) << 4));
}

template<bool RESID, bool DUAL, bool SPLITQ, bool BATCHB>
__global__ __launch_bounds__(256)
void gemm_mma(const __nv_bfloat16* __restrict__ Ah, const __nv_bfloat16* __restrict__ Al,
              const __nv_bfloat16* __restrict__ Bh1, const __nv_bfloat16* __restrict__ Bl1,
              const __nv_bfloat16* __restrict__ Bh2, const __nv_bfloat16* __restrict__ Bl2,
              const float* __restrict__ bias1, const float* __restrict__ bias2,
              float* __restrict__ C1, float* __restrict__ C2,
              const float* __restrict__ resid,
              __nv_bfloat16* __restrict__ qh, __nv_bfloat16* __restrict__ ql)
{
    extern __shared__ char dsm[];
    char* smem = (char*)(((uintptr_t)dsm + 127) & ~(uintptr_t)127);
    const uint32_t sbase = smem_to_u32(smem);

    const int tid = threadIdx.x;
    const int lane = tid & 31, wid = tid >> 5;
    const int m0 = blockIdx.y * 128;
    const int wm = (wid >> 2) * 64;
    const int wn = (wid & 3) * 32;

    const int nb = blockIdx.x;
    const __nv_bfloat16 *Bh, *Bl;
    const float* bias;
    float* C;
    int n0;
    bool emit_split = SPLITQ;
    if (DUAL && nb >= 8) {
        Bh = Bh2; Bl = Bl2; bias = bias2; C = C2; n0 = (nb - 8) * 128;
        emit_split = false;
    } else {
        Bh = Bh1; Bl = Bl1; bias = bias1; C = C1; n0 = nb * 128;
    }
    if (BATCHB) {
        const size_t boff = (size_t)(m0 / SS) * DD * DD;
        Bh += boff; Bl += boff;
    }

    const __nv_bfloat16* srcs[4] = {Ah, Al, Bh, Bl};

    float acc[4][4][4];
    #pragma unroll
    for (int i = 0; i < 4; i++)
        #pragma unroll
        for (int j = 0; j < 4; j++)
            #pragma unroll
            for (int v = 0; v < 4; v++) acc[i][j][v] = 0.f;

    auto fill = [&](int slot, int t) {
        const int k0 = t * BKT;
        const uint32_t stage_base = sbase + slot * STAGE_BYTES;
        #pragma unroll
        for (int a = 0; a < 4; a++) {
            const __nv_bfloat16* src = srcs[a];
            const int r0 = (a < 2) ? m0 : n0;
            const uint32_t abase = stage_base + a * ARR_BYTES;
            #pragma unroll
            for (int i = 0; i < 2; i++) {
                int idx = tid + i * 256;
                int row = idx >> 2;
                int c = idx & 3;
                cp16(abase + sw_off(row, c),
                     src + (size_t)(r0 + row) * DD + k0 + c * 8);
            }
        }
    };

    auto compute = [&](int slot) {
        const uint32_t stage_base = sbase + slot * STAGE_BYTES;
        #pragma unroll
        for (int ks = 0; ks < 2; ks++) {
            uint32_t ahf[4][4], alf[4][4], bhf[4][2], blf[4][2];
            #pragma unroll
            for (int p = 0; p < 2; p++) {
                int row = wn + p * 16 + ((lane >> 4) << 3) + (lane & 7);
                int ch = ks * 2 + ((lane >> 3) & 1);
                uint32_t r[4];
                ldsm4(r, stage_base + 2 * ARR_BYTES + sw_off(row, ch));
                bhf[p*2][0] = r[0]; bhf[p*2][1] = r[1];
                bhf[p*2+1][0] = r[2]; bhf[p*2+1][1] = r[3];
                ldsm4(r, stage_base + 3 * ARR_BYTES + sw_off(row, ch));
                blf[p*2][0] = r[0]; blf[p*2][1] = r[1];
                blf[p*2+1][0] = r[2]; blf[p*2+1][1] = r[3];
            }
            #pragma unroll
            for (int mt = 0; mt < 4; mt++) {
                int row = wm + mt * 16 + (lane & 15);
                int ch = ks * 2 + (lane >> 4);
                ldsm4(ahf[mt], stage_base + 0 * ARR_BYTES + sw_off(row, ch));
                ldsm4(alf[mt], stage_base + 1 * ARR_BYTES + sw_off(row, ch));
            }
            #pragma unroll
            for (int mt = 0; mt < 4; mt++)
                #pragma unroll
                for (int nt = 0; nt < 4; nt++)
                    mma16816(acc[mt][nt], ahf[mt], bhf[nt]);
            #pragma unroll
            for (int mt = 0; mt < 4; mt++)
                #pragma unroll
                for (int nt = 0; nt < 4; nt++)
                    mma16816(acc[mt][nt], ahf[mt], blf[nt]);
            #pragma unroll
            for (int mt = 0; mt < 4; mt++)
                #pragma unroll
                for (int nt = 0; nt < 4; nt++)
                    mma16816(acc[mt][nt], alf[mt], bhf[nt]);
        }
    };

    fill(0, 0); CP_COMMIT();
    fill(1, 1); CP_COMMIT();

    for (int t = 0; t < NKT2; t++) {
        if (t + 1 < NKT2) { CP_WAIT(1); } else { CP_WAIT(0); }
        __syncthreads();
        if (t + 2 < NKT2) {
            fill((t + 2) % NST, t + 2);
            CP_COMMIT();
        }
        compute(t % NST);
    }

    // ---- epilogue ----
    #pragma unroll
    for (int mt = 0; mt < 4; mt++) {
        #pragma unroll
        for (int nt = 0; nt < 4; nt++) {
            int r = m0 + wm + mt * 16 + (lane >> 2);
            int c = n0 + wn + nt * 8 + (lane & 3) * 2;
            float2 bv = *(const float2*)&bias[c];
            #pragma unroll
            for (int half = 0; half < 2; half++) {
                int rr = r + half * 8;
                const size_t off = (size_t)rr * DD + c;
                float2 o;
                o.x = acc[mt][nt][half * 2 + 0] + bv.x;
                o.y = acc[mt][nt][half * 2 + 1] + bv.y;
                if (RESID) {
                    float2 qv = *(const float2*)&resid[off];
                    o.x += qv.x; o.y += qv.y;
                }
                *(float2*)&C[off] = o;
                if (SPLITQ && emit_split) {
                    __nv_bfloat16 h0, l0, h1, l1;
                    split1(o.x, h0, l0);
                    split1(o.y, h1, l1);
                    *(__nv_bfloat162*)&qh[off] = __nv_bfloat162(h0, h1);
                    *(__nv_bfloat162*)&ql[off] = __nv_bfloat162(l0, l1);
                }
            }
        }
    }
}

// ---------------------------------------------------------------------------
// Wqa2 = Wq @ Wqa  [1024 x 16]  (thread per (row, head), 4 acc chains)
// ---------------------------------------------------------------------------
__global__ __launch_bounds__(256)
void wqa2_kernel(const float* __restrict__ Wq, const float* __restrict__ Wqa)
{
    const int h = threadIdx.x & 15;
    const int r = threadIdx.x >> 4;
    const int row = blockIdx.x * 16 + r;
    const float* wrow = &Wq[(size_t)row * DD];

    float a0 = 0.f, a1 = 0.f, a2 = 0.f, a3 = 0.f;
    #pragma unroll 2
    for (int k = 0; k < DD; k += 16) {
        float4 q0 = *(const float4*)&wrow[k + 0];
        float4 q1 = *(const float4*)&wrow[k + 4];
        float4 q2 = *(const float4*)&wrow[k + 8];
        float4 q3 = *(const float4*)&wrow[k + 12];
        a0 = fmaf(q0.x, Wqa[(k + 0)  * HH + h], a0);
        a0 = fmaf(q0.y, Wqa[(k + 1)  * HH + h], a0);
        a0 = fmaf(q0.z, Wqa[(k + 2)  * HH + h], a0);
        a0 = fmaf(q0.w, Wqa[(k + 3)  * HH + h], a0);
        a1 = fmaf(q1.x, Wqa[(k + 4)  * HH + h], a1);
        a1 = fmaf(q1.y, Wqa[(k + 5)  * HH + h], a1);
        a1 = fmaf(q1.z, Wqa[(k + 6)  * HH + h], a1);
        a1 = fmaf(q1.w, Wqa[(k + 7)  * HH + h], a1);
        a2 = fmaf(q2.x, Wqa[(k + 8)  * HH + h], a2);
        a2 = fmaf(q2.y, Wqa[(k + 9)  * HH + h], a2);
        a2 = fmaf(q2.z, Wqa[(k + 10) * HH + h], a2);
        a2 = fmaf(q2.w, Wqa[(k + 11) * HH + h], a2);
        a3 = fmaf(q3.x, Wqa[(k + 12) * HH + h], a3);
        a3 = fmaf(q3.y, Wqa[(k + 13) * HH + h], a3);
        a3 = fmaf(q3.z, Wqa[(k + 14) * HH + h], a3);
        a3 = fmaf(q3.w, Wqa[(k + 15) * HH + h], a3);
    }
    g_wqa2[row * HH + h] = (a0 + a1) + (a2 + a3);
}

// bias2[h] = bq @ Wqa[:,h] + bqa[h]   (one block, 256 threads: 16 kparts x 16 h)
__global__ __launch_bounds__(256)
void bias2_kernel(const float* __restrict__ bq, const float* __restrict__ Wqa,
                  const float* __restrict__ bqa)
{
    __shared__ float part[16][16];
    const int h = threadIdx.x & 15;
    const int kp = threadIdx.x >> 4;
    float acc = 0.f;
    for (int k = kp * 64; k < kp * 64 + 64; k++)
        acc = fmaf(bq[k], Wqa[k * HH + h], acc);
    part[kp][h] = acc;
    __syncthreads();
    if (threadIdx.x < HH) {
        float s = 0.f;
        #pragma unroll
        for (int i = 0; i < 16; i++) s += part[i][threadIdx.x];
        g_bias2[threadIdx.x] = s + bqa[threadIdx.x];
    }
}

// ---------------------------------------------------------------------------
// split fp32 -> bf16 hi/lo (hs), FUSED with qa = hs @ Wqa2 + bias2.
// One block = one hs row (256 thr x 4 elems). Wqa2 is 64KB, L1-resident.
// ---------------------------------------------------------------------------
__global__ __launch_bounds__(256)
void split_qa_kernel(const float* __restrict__ x, __nv_bfloat16* __restrict__ hi,
                     __nv_bfloat16* __restrict__ lo)
{
    __shared__ float wsum[8][HH];

    const int tid = threadIdx.x;
    const int lane = tid & 31, warp = tid >> 5;
    const size_t row = blockIdx.x;
    const size_t e = row * DD + tid * 4;
    const int k0 = tid * 4;

    float4 v = *(const float4*)(x + e);

    // split
    __nv_bfloat16 h0, h1, h2, h3, l0, l1, l2, l3;
    split1(v.x, h0, l0); split1(v.y, h1, l1); split1(v.z, h2, l2); split1(v.w, h3, l3);
    *(__nv_bfloat162*)(hi + e)     = __nv_bfloat162(h0, h1);
    *(__nv_bfloat162*)(hi + e + 2) = __nv_bfloat162(h2, h3);
    *(__nv_bfloat162*)(lo + e)     = __nv_bfloat162(l0, l1);
    *(__nv_bfloat162*)(lo + e + 2) = __nv_bfloat162(l2, l3);

    // qa partials: p[h] = sum of 4 elems against Wqa2 rows k0..k0+3
    float p[HH];
    {
        const float4* w0 = (const float4*)&g_wqa2[(k0 + 0) * HH];
        const float4* w1 = (const float4*)&g_wqa2[(k0 + 1) * HH];
        const float4* w2 = (const float4*)&g_wqa2[(k0 + 2) * HH];
        const float4* w3 = (const float4*)&g_wqa2[(k0 + 3) * HH];
        #pragma unroll
        for (int j = 0; j < 4; j++) {
            float4 a = w0[j], b = w1[j], c = w2[j], d = w3[j];
            p[j*4+0] = v.x*a.x + v.y*b.x + v.z*c.x + v.w*d.x;
            p[j*4+1] = v.x*a.y + v.y*b.y + v.z*c.y + v.w*d.y;
            p[j*4+2] = v.x*a.z + v.y*b.z + v.z*c.z + v.w*d.z;
            p[j*4+3] = v.x*a.w + v.y*b.w + v.z*c.w + v.w*d.w;
        }
    }
    // warp reduce each head
    #pragma unroll
    for (int h = 0; h < HH; h++) {
        #pragma unroll
        for (int o = 16; o; o >>= 1)
            p[h] += __shfl_xor_sync(0xffffffffu, p[h], o);
    }
    if (lane < HH) wsum[warp][lane] = p[lane];
    __syncthreads();
    if (tid < HH) {
        float s = 0.f;
        #pragma unroll
        for (int i = 0; i < 8; i++) s += wsum[i][tid];
        g_qa[row * HH + tid] = s + g_bias2[tid];
    }
}

// W[K][N] fp32 -> B[N][K] bf16 hi/lo (transpose + split)
__global__ __launch_bounds__(256)
void wsplit_kernel(const float* __restrict__ W, __nv_bfloat16* __restrict__ Bh,
                   __nv_bfloat16* __restrict__ Bl)
{
    __shared__ float t[32][33];
    const int tx = threadIdx.x, ty = threadIdx.y;
    const int nx = blockIdx.x * 32, ky = blockIdx.y * 32;
    #pragma unroll
    for (int i = 0; i < 4; i++)
        t[ty + 8 * i][tx] = W[(size_t)(ky + ty + 8 * i) * DD + nx + tx];
    __syncthreads();
    #pragma unroll
    for (int i = 0; i < 4; i++) {
        float v = t[tx][ty + 8 * i];
        __nv_bfloat16 h, l;
        split1(v, h, l);
        size_t o = (size_t)(nx + ty + 8 * i) * DD + ky + tx;
        Bh[o] = h; Bl[o] = l;
    }
}

// per-batch scaled weight: out[b][n][k] = split(W[k][n] * pk[b][k]), grid.z = batch
__global__ __launch_bounds__(256)
void wsplit_scaled_kernel(const float* __restrict__ W, const float* __restrict__ pk,
                          __nv_bfloat16* __restrict__ Bh, __nv_bfloat16* __restrict__ Bl)
{
    __shared__ float t[32][33];
    const int tx = threadIdx.x, ty = threadIdx.y;
    const int nx = blockIdx.x * 32, ky = blockIdx.y * 32;
    const int b = blockIdx.z;
    #pragma unroll
    for (int i = 0; i < 4; i++)
        t[ty + 8 * i][tx] = W[(size_t)(ky + ty + 8 * i) * DD + nx + tx];
    __syncthreads();
    const float s = pk[b * DD + ky + tx];
    const size_t bo = (size_t)b * DD * DD;
    #pragma unroll
    for (int i = 0; i < 4; i++) {
        float v = t[tx][ty + 8 * i] * s;
        __nv_bfloat16 h, l;
        split1(v, h, l);
        size_t o = bo + (size_t)(nx + ty + 8 * i) * DD + ky + tx;
        Bh[o] = h; Bl[o] = l;
    }
}

// ---------------------------------------------------------------------------
// pool_q / pool_k (exact best-config forms)
// ---------------------------------------------------------------------------
__global__ __launch_bounds__(256)
void pool_q_kernel(const float* __restrict__ mask)
{
    __shared__ float w[SS];
    __shared__ float red[8];
    __shared__ float part[4][DHH];
    const int b = blockIdx.x / HH, h = blockIdx.x % HH;
    const int tid = threadIdx.x;
    const float scale = 0.125f;

    float lmax = -1e30f;
    for (int s = tid; s < SS; s += 256) {
        float sc = g_qa[((size_t)b * SS + s) * HH + h] * scale + mask[b * SS + s];
        w[s] = sc;
        lmax = fmaxf(lmax, sc);
    }
    #pragma unroll
    for (int o = 16; o; o >>= 1) lmax = fmaxf(lmax, __shfl_xor_sync(0xffffffffu, lmax, o));
    if ((tid & 31) == 0) red[tid >> 5] = lmax;
    __syncthreads();
    float gmax = red[0];
    #pragma unroll
    for (int i = 1; i < 8; i++) gmax = fmaxf(gmax, red[i]);
    __syncthreads();

    float lsum = 0.f;
    for (int s = tid; s < SS; s += 256) { float e = expf(w[s] - gmax); w[s] = e; lsum += e; }
    #pragma unroll
    for (int o = 16; o; o >>= 1) lsum += __shfl_xor_sync(0xffffffffu, lsum, o);
    if ((tid & 31) == 0) red[tid >> 5] = lsum;
    __syncthreads();
    float gsum = 0.f;
    #pragma unroll
    for (int i = 0; i < 8; i++) gsum += red[i];
    const float inv = 1.0f / gsum;

    const int dh = tid & 63, sg = tid >> 6;
    float acc = 0.f;
    for (int s = sg; s < SS; s += 4)
        acc = fmaf(w[s], g_q[((size_t)b * SS + s) * DD + h * DHH + dh], acc);
    part[sg][dh] = acc;
    __syncthreads();
    if (tid < DHH)
        g_pq[b * DD + h * DHH + tid] =
            (part[0][tid] + part[1][tid] + part[2][tid] + part[3][tid]) * inv;
}

__global__ __launch_bounds__(256)
void pool_k_kernel(const float* __restrict__ mask)
{
    __shared__ float w[SS];
    __shared__ float red[8];
    __shared__ float part[4][DHH];
    __shared__ float pq[DHH];
    const int b = blockIdx.x / HH, h = blockIdx.x % HH;
    const int tid = threadIdx.x;
    const int lane = tid & 31, warp = tid >> 5;

    if (tid < DHH) pq[tid] = g_pq[b * DD + h * DHH + tid];
    __syncthreads();

    for (int s = warp; s < SS; s += 8) {
        const float* krow = &g_k[((size_t)b * SS + s) * DD + h * DHH];
        float p = krow[lane] * pq[lane] + krow[lane + 32] * pq[lane + 32];
        #pragma unroll
        for (int o = 16; o; o >>= 1) p += __shfl_xor_sync(0xffffffffu, p, o);
        if (lane == 0) w[s] = p * 0.125f + mask[b * SS + s];
    }
    __syncthreads();

    float lmax = -1e30f;
    for (int s = tid; s < SS; s += 256) lmax = fmaxf(lmax, w[s]);
    #pragma unroll
    for (int o = 16; o; o >>= 1) lmax = fmaxf(lmax, __shfl_xor_sync(0xffffffffu, lmax, o));
    if ((tid & 31) == 0) red[tid >> 5] = lmax;
    __syncthreads();
    float gmax = red[0];
    #pragma unroll
    for (int i = 1; i < 8; i++) gmax = fmaxf(gmax, red[i]);
    __syncthreads();

    float lsum = 0.f;
    for (int s = tid; s < SS; s += 256) { float e = expf(w[s] - gmax); w[s] = e; lsum += e; }
    #pragma unroll
    for (int o = 16; o; o >>= 1) lsum += __shfl_xor_sync(0xffffffffu, lsum, o);
    if ((tid & 31) == 0) red[tid >> 5] = lsum;
    __syncthreads();
    float gsum = 0.f;
    #pragma unroll
    for (int i = 0; i < 8; i++) gsum += red[i];
    const float inv = 1.0f / gsum;

    const int dh = tid & 63, sg = tid >> 6;
    float acc = 0.f;
    for (int s = sg; s < SS; s += 4)
        acc = fmaf(w[s], g_k[((size_t)b * SS + s) * DD + h * DHH + dh], acc);
    part[sg][dh] = acc;
    __syncthreads();
    if (tid < DHH)
        g_pk[b * DD + h * DHH + tid] =
            (part[0][tid] + part[1][tid] + part[2][tid] + part[3][tid]) * inv;
}

// ---------------------------------------------------------------------------
extern "C" void kernel_launch(void* const* d_in, const int* in_sizes, int n_in,
                              void* d_out, int out_size)
{
    const float* hs   = (const float*)d_in[0];
    const float* mask = (const float*)d_in[1];
    const float* Wq   = (const float*)d_in[2];
    const float* bq   = (const float*)d_in[3];
    const float* Wqa  = (const float*)d_in[4];
    const float* bqa  = (const float*)d_in[5];
    const float* Wk   = (const float*)d_in[6];
    const float* bk   = (const float*)d_in[7];
    const float* Wt   = (const float*)d_in[8];
    const float* bt   = (const float*)d_in[9];
    float* out = (float*)d_out;

    float *q, *k, *pk;
    __nv_bfloat16 *ah, *al, *qh, *ql, *wh1, *wl1, *wh2, *wl2, *wth8, *wtl8;
    cudaGetSymbolAddress((void**)&q,    g_q);
    cudaGetSymbolAddress((void**)&k,    g_k);
    cudaGetSymbolAddress((void**)&pk,   g_pk);
    cudaGetSymbolAddress((void**)&ah,   g_ah);
    cudaGetSymbolAddress((void**)&al,   g_al);
    cudaGetSymbolAddress((void**)&qh,   g_qh);
    cudaGetSymbolAddress((void**)&ql,   g_ql);
    cudaGetSymbolAddress((void**)&wh1,  g_wh1);
    cudaGetSymbolAddress((void**)&wl1,  g_wl1);
    cudaGetSymbolAddress((void**)&wh2,  g_wh2);
    cudaGetSymbolAddress((void**)&wl2,  g_wl2);
    cudaGetSymbolAddress((void**)&wth8, g_wth8);
    cudaGetSymbolAddress((void**)&wtl8, g_wtl8);

    cudaFuncSetAttribute(gemm_mma<false, true, true, false>,
                         cudaFuncAttributeMaxDynamicSharedMemorySize, GEMM_SMEM);
    cudaFuncSetAttribute(gemm_mma<true, false, false, true>,
                         cudaFuncAttributeMaxDynamicSharedMemorySize, GEMM_SMEM);

    dim3 wgrid(DD / 32, DD / 32), wblk(32, 8);
    dim3 wsgrid(DD / 32, DD / 32, BB);
    dim3 ggrid_dual(16, M_TOT / 128);
    dim3 ggrid(8, M_TOT / 128);

    // qa precompute (depends only on inputs)
    wqa2_kernel<<<DD / 16, 256>>>(Wq, Wqa);
    bias2_kernel<<<1, 256>>>(bq, Wqa, bqa);

    // split(hs) fused with qa = hs @ Wqa2 + bias2
    split_qa_kernel<<<M_TOT, 256>>>(hs, ah, al);

    wsplit_kernel<<<wgrid, wblk>>>(Wq, wh1, wl1);
    wsplit_kernel<<<wgrid, wblk>>>(Wk, wh2, wl2);

    // fused q+k projection; q-half stores fp32 q AND emits split(q)
    gemm_mma<false, true, true, false><<<ggrid_dual, 256, GEMM_SMEM>>>(
        ah, al, wh1, wl1, wh2, wl2, bq, bk, q, k, nullptr, qh, ql);

    pool_q_kernel<<<BB * HH, 256>>>(mask);
    pool_k_kernel<<<BB * HH, 256>>>(mask);

    // per-batch scaled transform weights
    wsplit_scaled_kernel<<<wsgrid, wblk>>>(Wt, pk, wth8, wtl8);

    // out = q @ (diag(pk[b]) Wt) + bt + q
    gemm_mma<true, false, false, true><<<ggrid, 256, GEMM_SMEM>>>(
        qh, ql, wth8, wtl8, wth8, wtl8, bt, bt, out, out, q, nullptr, nullptr);
}

// round 16
// speedup vs baseline: 2.2406x; 2.2406x over previous
#include <cuda_runtime.h>
#include <cuda_fp16.h>
#include <math.h>
#include <stdint.h>

#define BB 8
#define SS 2048
#define DD 1024
#define HH 16
#define DHH 64
#define M_TOT (BB*SS)

// ---------------------------------------------------------------------------
// Device scratch (allocation-free rule)
// ---------------------------------------------------------------------------
__device__ float g_q[(size_t)M_TOT * DD];            // fp32 q (qa/pool/residual)
__device__ float g_k[(size_t)M_TOT * DD];
__device__ float g_qa[(size_t)M_TOT * HH];           // [row][h]
__device__ float g_pq[BB * DD];
__device__ float g_pk[BB * DD];
__device__ __half g_ah[(size_t)M_TOT * DD];          // fp16(hs)
__device__ __half g_qh[(size_t)M_TOT * DD];          // fp16(q), from gemm1 epilogue
__device__ __half g_wh1[DD * DD];                    // fp16(Wq^T)  (N-major, K contig)
__device__ __half g_wh2[DD * DD];                    // fp16(Wk^T)
__device__ __half g_wth8[(size_t)BB * DD * DD];      // fp16((diag(pk[b])*Wt)^T)

// ---------------------------------------------------------------------------
// PTX helpers (sm_103-safe: mma.sync / ldmatrix / cp.async only)
// ---------------------------------------------------------------------------
__device__ __forceinline__ uint32_t smem_to_u32(const void* p) {
    uint32_t a;
    asm("{ .reg .u64 t; cvta.to.shared.u64 t, %1; cvt.u32.u64 %0, t; }" : "=r"(a) : "l"(p));
    return a;
}
__device__ __forceinline__ void cp16(uint32_t s, const void* g) {
    asm volatile("cp.async.cg.shared.global [%0], [%1], 16;" :: "r"(s), "l"(g));
}
#define CP_COMMIT() asm volatile("cp.async.commit_group;" ::: "memory")
#define CP_WAIT(n)  asm volatile("cp.async.wait_group %0;" :: "n"(n) : "memory")

__device__ __forceinline__ void ldsm4(uint32_t* r, uint32_t a) {
    asm volatile("ldmatrix.sync.aligned.m8n8.x4.shared.b16 {%0,%1,%2,%3}, [%4];"
                 : "=r"(r[0]), "=r"(r[1]), "=r"(r[2]), "=r"(r[3]) : "r"(a));
}
__device__ __forceinline__ void mma16816(float* c, const uint32_t* a, const uint32_t* b) {
    asm volatile("mma.sync.aligned.m16n8k16.row.col.f32.f16.f16.f32 "
                 "{%0,%1,%2,%3}, {%4,%5,%6,%7}, {%8,%9}, {%0,%1,%2,%3};"
                 : "+f"(c[0]), "+f"(c[1]), "+f"(c[2]), "+f"(c[3])
                 : "r"(a[0]), "r"(a[1]), "r"(a[2]), "r"(a[3]), "r"(b[0]), "r"(b[1]));
}

// ---------------------------------------------------------------------------
// fp16 GEMM via mma.sync: 128x128 CTA tile, BK=32, 256 threads,
// 8 warps 2x4 -> warp tile 64x32, 3-stage cp.async ring, one sync per K-step.
// DUAL:   grid.x=16 -> CTAs 0-7 use B1->C1, 8-15 use B2->C2.
// EMITH:  C1-half CTAs also emit fp16(C) into qh.
// RESID:  adds fp32 resid in epilogue.
// BATCHB: B pointer advanced by batch(m0)*DD*DD.
// ---------------------------------------------------------------------------
#define BKT 32
#define NKT2 (DD / BKT)          // 32
#define ARR_BYTES 8192           // 128 rows x 64B
#define STAGE_BYTES (2 * ARR_BYTES)
#define NST 3
#define GEMM_SMEM (NST * STAGE_BYTES + 128)

__device__ __forceinline__ uint32_t sw_off(int row, int chunk) {
    return (uint32_t)(row * 64 + ((chunk ^ ((row >> 1) & 3)) << 4));
}

template<bool RESID, bool DUAL, bool EMITH, bool BATCHB>
__global__ __launch_bounds__(256)
void gemm_mma(const __half* __restrict__ A,
              const __half* __restrict__ B1, const __half* __restrict__ B2,
              const float* __restrict__ bias1, const float* __restrict__ bias2,
              float* __restrict__ C1, float* __restrict__ C2,
              const float* __restrict__ resid, __half* __restrict__ qh)
{
    extern __shared__ char dsm[];
    char* smem = (char*)(((uintptr_t)dsm + 127) & ~(uintptr_t)127);
    const uint32_t sbase = smem_to_u32(smem);

    const int tid = threadIdx.x;
    const int lane = tid & 31, wid = tid >> 5;
    const int m0 = blockIdx.y * 128;
    const int wm = (wid >> 2) * 64;
    const int wn = (wid & 3) * 32;

    const int nb = blockIdx.x;
    const __half* B;
    const float* bias;
    float* C;
    int n0;
    bool emit_h = EMITH;
    if (DUAL && nb >= 8) {
        B = B2; bias = bias2; C = C2; n0 = (nb - 8) * 128;
        emit_h = false;
    } else {
        B = B1; bias = bias1; C = C1; n0 = nb * 128;
    }
    if (BATCHB) B += (size_t)(m0 / SS) * DD * DD;

    float acc[4][4][4];
    #pragma unroll
    for (int i = 0; i < 4; i++)
        #pragma unroll
        for (int j = 0; j < 4; j++)
            #pragma unroll
            for (int v = 0; v < 4; v++) acc[i][j][v] = 0.f;

    auto fill = [&](int slot, int t) {
        const int k0 = t * BKT;
        const uint32_t stage_base = sbase + slot * STAGE_BYTES;
        #pragma unroll
        for (int a = 0; a < 2; a++) {
            const __half* src = a ? B : A;
            const int r0 = a ? n0 : m0;
            const uint32_t abase = stage_base + a * ARR_BYTES;
            #pragma unroll
            for (int i = 0; i < 2; i++) {
                int idx = tid + i * 256;
                int row = idx >> 2;
                int c = idx & 3;
                cp16(abase + sw_off(row, c),
                     src + (size_t)(r0 + row) * DD + k0 + c * 8);
            }
        }
    };

    auto compute = [&](int slot) {
        const uint32_t stage_base = sbase + slot * STAGE_BYTES;
        #pragma unroll
        for (int ks = 0; ks < 2; ks++) {
            uint32_t ahf[4][4], bhf[4][2];
            #pragma unroll
            for (int p = 0; p < 2; p++) {
                int row = wn + p * 16 + ((lane >> 4) << 3) + (lane & 7);
                int ch = ks * 2 + ((lane >> 3) & 1);
                uint32_t r[4];
                ldsm4(r, stage_base + ARR_BYTES + sw_off(row, ch));
                bhf[p*2][0] = r[0]; bhf[p*2][1] = r[1];
                bhf[p*2+1][0] = r[2]; bhf[p*2+1][1] = r[3];
            }
            #pragma unroll
            for (int mt = 0; mt < 4; mt++) {
                int row = wm + mt * 16 + (lane & 15);
                int ch = ks * 2 + (lane >> 4);
                ldsm4(ahf[mt], stage_base + sw_off(row, ch));
            }
            #pragma unroll
            for (int mt = 0; mt < 4; mt++)
                #pragma unroll
                for (int nt = 0; nt < 4; nt++)
                    mma16816(acc[mt][nt], ahf[mt], bhf[nt]);
        }
    };

    fill(0, 0); CP_COMMIT();
    fill(1, 1); CP_COMMIT();

    for (int t = 0; t < NKT2; t++) {
        if (t + 1 < NKT2) { CP_WAIT(1); } else { CP_WAIT(0); }
        __syncthreads();
        if (t + 2 < NKT2) {
            fill((t + 2) % NST, t + 2);
            CP_COMMIT();
        }
        compute(t % NST);
    }

    // ---- epilogue ----
    #pragma unroll
    for (int mt = 0; mt < 4; mt++) {
        #pragma unroll
        for (int nt = 0; nt < 4; nt++) {
            int r = m0 + wm + mt * 16 + (lane >> 2);
            int c = n0 + wn + nt * 8 + (lane & 3) * 2;
            float2 bv = *(const float2*)&bias[c];
            #pragma unroll
            for (int half = 0; half < 2; half++) {
                int rr = r + half * 8;
                const size_t off = (size_t)rr * DD + c;
                float2 o;
                o.x = acc[mt][nt][half * 2 + 0] + bv.x;
                o.y = acc[mt][nt][half * 2 + 1] + bv.y;
                if (RESID) {
                    float2 qv = *(const float2*)&resid[off];
                    o.x += qv.x; o.y += qv.y;
                }
                *(float2*)&C[off] = o;
                if (EMITH && emit_h)
                    *(__half2*)&qh[off] = __floats2half2_rn(o.x, o.y);
            }
        }
    }
}

// ---------------------------------------------------------------------------
// fp32 -> fp16 convert (hs)
// ---------------------------------------------------------------------------
__global__ __launch_bounds__(256)
void cvt_kernel(const float* __restrict__ x, __half* __restrict__ y)
{
    size_t e = ((size_t)blockIdx.x * 256 + threadIdx.x) * 4;
    float4 v = *(const float4*)(x + e);
    *(__half2*)(y + e)     = __floats2half2_rn(v.x, v.y);
    *(__half2*)(y + e + 2) = __floats2half2_rn(v.z, v.w);
}

// W[K][N] fp32 -> B[N][K] fp16 (transpose + convert)
__global__ __launch_bounds__(256)
void wcvt_kernel(const float* __restrict__ W, __half* __restrict__ Bh)
{
    __shared__ float t[32][33];
    const int tx = threadIdx.x, ty = threadIdx.y;
    const int nx = blockIdx.x * 32, ky = blockIdx.y * 32;
    #pragma unroll
    for (int i = 0; i < 4; i++)
        t[ty + 8 * i][tx] = W[(size_t)(ky + ty + 8 * i) * DD + nx + tx];
    __syncthreads();
    #pragma unroll
    for (int i = 0; i < 4; i++)
        Bh[(size_t)(nx + ty + 8 * i) * DD + ky + tx] = __float2half_rn(t[tx][ty + 8 * i]);
}

// per-batch scaled weight: out[b][n][k] = fp16(W[k][n] * pk[b][k]), grid.z = batch
__global__ __launch_bounds__(256)
void wcvt_scaled_kernel(const float* __restrict__ W, const float* __restrict__ pk,
                        __half* __restrict__ Bh)
{
    __shared__ float t[32][33];
    const int tx = threadIdx.x, ty = threadIdx.y;
    const int nx = blockIdx.x * 32, ky = blockIdx.y * 32;
    const int b = blockIdx.z;
    #pragma unroll
    for (int i = 0; i < 4; i++)
        t[ty + 8 * i][tx] = W[(size_t)(ky + ty + 8 * i) * DD + nx + tx];
    __syncthreads();
    const float s = pk[b * DD + ky + tx];
    const size_t bo = (size_t)b * DD * DD;
    #pragma unroll
    for (int i = 0; i < 4; i++)
        Bh[bo + (size_t)(nx + ty + 8 * i) * DD + ky + tx] =
            __float2half_rn(t[tx][ty + 8 * i] * s);
}

// ---------------------------------------------------------------------------
// qa = q @ Wqa + bqa  (R14 form: thread per (row, head), 4 acc chains)
// ---------------------------------------------------------------------------
__global__ __launch_bounds__(256)
void qa_kernel(const float* __restrict__ Wqa, const float* __restrict__ bqa)
{
    const int h = threadIdx.x & 15;
    const int r = threadIdx.x >> 4;
    const int row = blockIdx.x * 16 + r;
    const float* qrow = &g_q[(size_t)row * DD];

    float a0 = 0.f, a1 = 0.f, a2 = 0.f, a3 = 0.f;
    #pragma unroll 2
    for (int k = 0; k < DD; k += 16) {
        float4 q0 = *(const float4*)&qrow[k + 0];
        float4 q1 = *(const float4*)&qrow[k + 4];
        float4 q2 = *(const float4*)&qrow[k + 8];
        float4 q3 = *(const float4*)&qrow[k + 12];
        a0 = fmaf(q0.x, Wqa[(k + 0)  * HH + h], a0);
        a0 = fmaf(q0.y, Wqa[(k + 1)  * HH + h], a0);
        a0 = fmaf(q0.z, Wqa[(k + 2)  * HH + h], a0);
        a0 = fmaf(q0.w, Wqa[(k + 3)  * HH + h], a0);
        a1 = fmaf(q1.x, Wqa[(k + 4)  * HH + h], a1);
        a1 = fmaf(q1.y, Wqa[(k + 5)  * HH + h], a1);
        a1 = fmaf(q1.z, Wqa[(k + 6)  * HH + h], a1);
        a1 = fmaf(q1.w, Wqa[(k + 7)  * HH + h], a1);
        a2 = fmaf(q2.x, Wqa[(k + 8)  * HH + h], a2);
        a2 = fmaf(q2.y, Wqa[(k + 9)  * HH + h], a2);
        a2 = fmaf(q2.z, Wqa[(k + 10) * HH + h], a2);
        a2 = fmaf(q2.w, Wqa[(k + 11) * HH + h], a2);
        a3 = fmaf(q3.x, Wqa[(k + 12) * HH + h], a3);
        a3 = fmaf(q3.y, Wqa[(k + 13) * HH + h], a3);
        a3 = fmaf(q3.z, Wqa[(k + 14) * HH + h], a3);
        a3 = fmaf(q3.w, Wqa[(k + 15) * HH + h], a3);
    }
    g_qa[(size_t)row * HH + h] = ((a0 + a1) + (a2 + a3)) + bqa[h];
}

// ---------------------------------------------------------------------------
// pool_q / pool_k (exact best-config forms)
// ---------------------------------------------------------------------------
__global__ __launch_bounds__(256)
void pool_q_kernel(const float* __restrict__ mask)
{
    __shared__ float w[SS];
    __shared__ float red[8];
    __shared__ float part[4][DHH];
    const int b = blockIdx.x / HH, h = blockIdx.x % HH;
    const int tid = threadIdx.x;
    const float scale = 0.125f;

    float lmax = -1e30f;
    for (int s = tid; s < SS; s += 256) {
        float sc = g_qa[((size_t)b * SS + s) * HH + h] * scale + mask[b * SS + s];
        w[s] = sc;
        lmax = fmaxf(lmax, sc);
    }
    #pragma unroll
    for (int o = 16; o; o >>= 1) lmax = fmaxf(lmax, __shfl_xor_sync(0xffffffffu, lmax, o));
    if ((tid & 31) == 0) red[tid >> 5] = lmax;
    __syncthreads();
    float gmax = red[0];
    #pragma unroll
    for (int i = 1; i < 8; i++) gmax = fmaxf(gmax, red[i]);
    __syncthreads();

    float lsum = 0.f;
    for (int s = tid; s < SS; s += 256) { float e = expf(w[s] - gmax); w[s] = e; lsum += e; }
    #pragma unroll
    for (int o = 16; o; o >>= 1) lsum += __shfl_xor_sync(0xffffffffu, lsum, o);
    if ((tid & 31) == 0) red[tid >> 5] = lsum;
    __syncthreads();
    float gsum = 0.f;
    #pragma unroll
    for (int i = 0; i < 8; i++) gsum += red[i];
    const float inv = 1.0f / gsum;

    const int dh = tid & 63, sg = tid >> 6;
    float acc = 0.f;
    for (int s = sg; s < SS; s += 4)
        acc = fmaf(w[s], g_q[((size_t)b * SS + s) * DD + h * DHH + dh], acc);
    part[sg][dh] = acc;
    __syncthreads();
    if (tid < DHH)
        g_pq[b * DD + h * DHH + tid] =
            (part[0][tid] + part[1][tid] + part[2][tid] + part[3][tid]) * inv;
}

__global__ __launch_bounds__(256)
void pool_k_kernel(const float* __restrict__ mask)
{
    __shared__ float w[SS];
    __shared__ float red[8];
    __shared__ float part[4][DHH];
    __shared__ float pq[DHH];
    const int b = blockIdx.x / HH, h = blockIdx.x % HH;
    const int tid = threadIdx.x;
    const int lane = tid & 31, warp = tid >> 5;

    if (tid < DHH) pq[tid] = g_pq[b * DD + h * DHH + tid];
    __syncthreads();

    for (int s = warp; s < SS; s += 8) {
        const float* krow = &g_k[((size_t)b * SS + s) * DD + h * DHH];
        float p = krow[lane] * pq[lane] + krow[lane + 32] * pq[lane + 32];
        #pragma unroll
        for (int o = 16; o; o >>= 1) p += __shfl_xor_sync(0xffffffffu, p, o);
        if (lane == 0) w[s] = p * 0.125f + mask[b * SS + s];
    }
    __syncthreads();

    float lmax = -1e30f;
    for (int s = tid; s < SS; s += 256) lmax = fmaxf(lmax, w[s]);
    #pragma unroll
    for (int o = 16; o; o >>= 1) lmax = fmaxf(lmax, __shfl_xor_sync(0xffffffffu, lmax, o));
    if ((tid & 31) == 0) red[tid >> 5] = lmax;
    __syncthreads();
    float gmax = red[0];
    #pragma unroll
    for (int i = 1; i < 8; i++) gmax = fmaxf(gmax, red[i]);
    __syncthreads();

    float lsum = 0.f;
    for (int s = tid; s < SS; s += 256) { float e = expf(w[s] - gmax); w[s] = e; lsum += e; }
    #pragma unroll
    for (int o = 16; o; o >>= 1) lsum += __shfl_xor_sync(0xffffffffu, lsum, o);
    if ((tid & 31) == 0) red[tid >> 5] = lsum;
    __syncthreads();
    float gsum = 0.f;
    #pragma unroll
    for (int i = 0; i < 8; i++) gsum += red[i];
    const float inv = 1.0f / gsum;

    const int dh = tid & 63, sg = tid >> 6;
    float acc = 0.f;
    for (int s = sg; s < SS; s += 4)
        acc = fmaf(w[s], g_k[((size_t)b * SS + s) * DD + h * DHH + dh], acc);
    part[sg][dh] = acc;
    __syncthreads();
    if (tid < DHH)
        g_pk[b * DD + h * DHH + tid] =
            (part[0][tid] + part[1][tid] + part[2][tid] + part[3][tid]) * inv;
}

// ---------------------------------------------------------------------------
extern "C" void kernel_launch(void* const* d_in, const int* in_sizes, int n_in,
                              void* d_out, int out_size)
{
    const float* hs   = (const float*)d_in[0];
    const float* mask = (const float*)d_in[1];
    const float* Wq   = (const float*)d_in[2];
    const float* bq   = (const float*)d_in[3];
    const float* Wqa  = (const float*)d_in[4];
    const float* bqa  = (const float*)d_in[5];
    const float* Wk   = (const float*)d_in[6];
    const float* bk   = (const float*)d_in[7];
    const float* Wt   = (const float*)d_in[8];
    const float* bt   = (const float*)d_in[9];
    float* out = (float*)d_out;

    float *q, *k, *pk;
    __half *ah, *qh, *wh1, *wh2, *wth8;
    cudaGetSymbolAddress((void**)&q,    g_q);
    cudaGetSymbolAddress((void**)&k,    g_k);
    cudaGetSymbolAddress((void**)&pk,   g_pk);
    cudaGetSymbolAddress((void**)&ah,   g_ah);
    cudaGetSymbolAddress((void**)&qh,   g_qh);
    cudaGetSymbolAddress((void**)&wh1,  g_wh1);
    cudaGetSymbolAddress((void**)&wh2,  g_wh2);
    cudaGetSymbolAddress((void**)&wth8, g_wth8);

    cudaFuncSetAttribute(gemm_mma<false, true, true, false>,
                         cudaFuncAttributeMaxDynamicSharedMemorySize, GEMM_SMEM);
    cudaFuncSetAttribute(gemm_mma<true, false, false, true>,
                         cudaFuncAttributeMaxDynamicSharedMemorySize, GEMM_SMEM);

    const int ncvt = (int)(((size_t)M_TOT * DD / 4) / 256);
    dim3 wgrid(DD / 32, DD / 32), wblk(32, 8);
    dim3 wsgrid(DD / 32, DD / 32, BB);
    dim3 ggrid_dual(16, M_TOT / 128);
    dim3 ggrid(8, M_TOT / 128);

    cvt_kernel<<<ncvt, 256>>>(hs, ah);
    wcvt_kernel<<<wgrid, wblk>>>(Wq, wh1);
    wcvt_kernel<<<wgrid, wblk>>>(Wk, wh2);

    // fused q+k projection; q-half stores fp32 q AND emits fp16 q
    gemm_mma<false, true, true, false><<<ggrid_dual, 256, GEMM_SMEM>>>(
        ah, wh1, wh2, bq, bk, q, k, nullptr, qh);

    qa_kernel<<<M_TOT / 16, 256>>>(Wqa, bqa);
    pool_q_kernel<<<BB * HH, 256>>>(mask);
    pool_k_kernel<<<BB * HH, 256>>>(mask);

    // per-batch scaled transform weights
    wcvt_scaled_kernel<<<wsgrid, wblk>>>(Wt, pk, wth8);

    // out = q @ (diag(pk[b]) Wt) + bt + q
    gemm_mma<true, false, false, true><<<ggrid, 256, GEMM_SMEM>>>(
        qh, wth8, wth8, bt, bt, out, out, q, nullptr);
}

// round 17
// speedup vs baseline: 2.2977x; 1.0255x over previous
#include <cuda_runtime.h>
#include <cuda_fp16.h>
#include <math.h>
#include <stdint.h>

#define BB 8
#define SS 2048
#define DD 1024
#define HH 16
#define DHH 64
#define M_TOT (BB*SS)

// ---------------------------------------------------------------------------
// Device scratch (allocation-free rule)
// ---------------------------------------------------------------------------
__device__ float g_q[(size_t)M_TOT * DD];            // fp32 q (qa/pool/residual)
__device__ float g_k[(size_t)M_TOT * DD];
__device__ float g_qa[(size_t)M_TOT * HH];           // [row][h]
__device__ float g_pq[BB * DD];
__device__ float g_pk[BB * DD];
__device__ __half g_ah[(size_t)M_TOT * DD];          // fp16(hs)
__device__ __half g_qh[(size_t)M_TOT * DD];          // fp16(q), from gemm1 epilogue
__device__ __half g_wh1[DD * DD];                    // fp16(Wq^T)  (N-major, K contig)
__device__ __half g_wh2[DD * DD];                    // fp16(Wk^T)
__device__ __half g_wth8[(size_t)BB * DD * DD];      // fp16((diag(pk[b])*Wt)^T)

// ---------------------------------------------------------------------------
// PTX helpers (sm_103-safe: mma.sync / ldmatrix / cp.async only)
// ---------------------------------------------------------------------------
__device__ __forceinline__ uint32_t smem_to_u32(const void* p) {
    uint32_t a;
    asm("{ .reg .u64 t; cvta.to.shared.u64 t, %1; cvt.u32.u64 %0, t; }" : "=r"(a) : "l"(p));
    return a;
}
__device__ __forceinline__ void cp16(uint32_t s, const void* g) {
    asm volatile("cp.async.cg.shared.global [%0], [%1], 16;" :: "r"(s), "l"(g));
}
#define CP_COMMIT() asm volatile("cp.async.commit_group;" ::: "memory")
#define CP_WAIT(n)  asm volatile("cp.async.wait_group %0;" :: "n"(n) : "memory")

__device__ __forceinline__ void ldsm4(uint32_t* r, uint32_t a) {
    asm volatile("ldmatrix.sync.aligned.m8n8.x4.shared.b16 {%0,%1,%2,%3}, [%4];"
                 : "=r"(r[0]), "=r"(r[1]), "=r"(r[2]), "=r"(r[3]) : "r"(a));
}
__device__ __forceinline__ void mma16816(float* c, const uint32_t* a, const uint32_t* b) {
    asm volatile("mma.sync.aligned.m16n8k16.row.col.f32.f16.f16.f32 "
                 "{%0,%1,%2,%3}, {%4,%5,%6,%7}, {%8,%9}, {%0,%1,%2,%3};"
                 : "+f"(c[0]), "+f"(c[1]), "+f"(c[2]), "+f"(c[3])
                 : "r"(a[0]), "r"(a[1]), "r"(a[2]), "r"(a[3]), "r"(b[0]), "r"(b[1]));
}

// ---------------------------------------------------------------------------
// fp16 GEMM via mma.sync: 128x128 CTA tile, BK=32, 128 threads,
// 4 warps 2x2 -> warp tile 64x64, 3-stage cp.async ring, one sync per K-step.
// DUAL:   grid.x=16 -> CTAs 0-7 use B1->C1, 8-15 use B2->C2.
// EMITH:  C1-half CTAs also emit fp16(C) into qh.
// RESID:  adds fp32 resid in epilogue.
// BATCHB: B pointer advanced by batch(m0)*DD*DD.
// ---------------------------------------------------------------------------
#define BKT 32
#define NKT2 (DD / BKT)          // 32
#define ARR_BYTES 8192           // 128 rows x 64B
#define STAGE_BYTES (2 * ARR_BYTES)
#define NST 3
#define GEMM_SMEM (NST * STAGE_BYTES + 128)

__device__ __forceinline__ uint32_t sw_off(int row, int chunk) {
    return (uint32_t)(row * 64 + ((chunk ^ ((row >> 1) & 3)) << 4));
}

template<bool RESID, bool DUAL, bool EMITH, bool BATCHB>
__global__ __launch_bounds__(128)
void gemm_mma(const __half* __restrict__ A,
              const __half* __restrict__ B1, const __half* __restrict__ B2,
              const float* __restrict__ bias1, const float* __restrict__ bias2,
              float* __restrict__ C1, float* __restrict__ C2,
              const float* __restrict__ resid, __half* __restrict__ qh)
{
    extern __shared__ char dsm[];
    char* smem = (char*)(((uintptr_t)dsm + 127) & ~(uintptr_t)127);
    const uint32_t sbase = smem_to_u32(smem);

    const int tid = threadIdx.x;
    const int lane = tid & 31, wid = tid >> 5;
    const int m0 = blockIdx.y * 128;
    const int wm = (wid >> 1) * 64;     // warp M offset (0 or 64)
    const int wn = (wid & 1) * 64;      // warp N offset (0 or 64)

    const int nb = blockIdx.x;
    const __half* B;
    const float* bias;
    float* C;
    int n0;
    bool emit_h = EMITH;
    if (DUAL && nb >= 8) {
        B = B2; bias = bias2; C = C2; n0 = (nb - 8) * 128;
        emit_h = false;
    } else {
        B = B1; bias = bias1; C = C1; n0 = nb * 128;
    }
    if (BATCHB) B += (size_t)(m0 / SS) * DD * DD;

    float acc[4][8][4];
    #pragma unroll
    for (int i = 0; i < 4; i++)
        #pragma unroll
        for (int j = 0; j < 8; j++)
            #pragma unroll
            for (int v = 0; v < 4; v++) acc[i][j][v] = 0.f;

    auto fill = [&](int slot, int t) {
        const int k0 = t * BKT;
        const uint32_t stage_base = sbase + slot * STAGE_BYTES;
        #pragma unroll
        for (int a = 0; a < 2; a++) {
            const __half* src = a ? B : A;
            const int r0 = a ? n0 : m0;
            const uint32_t abase = stage_base + a * ARR_BYTES;
            #pragma unroll
            for (int i = 0; i < 4; i++) {
                int idx = tid + i * 128;           // 0..511
                int row = idx >> 2;
                int c = idx & 3;
                cp16(abase + sw_off(row, c),
                     src + (size_t)(r0 + row) * DD + k0 + c * 8);
            }
        }
    };

    auto compute = [&](int slot) {
        const uint32_t stage_base = sbase + slot * STAGE_BYTES;
        #pragma unroll
        for (int ks = 0; ks < 2; ks++) {
            uint32_t ahf[4][4], bhf[8][2];
            // B fragments: 4 x4 loads cover 8 n-tiles of 8 rows
            #pragma unroll
            for (int p = 0; p < 4; p++) {
                int row = wn + p * 16 + ((lane >> 4) << 3) + (lane & 7);
                int ch = ks * 2 + ((lane >> 3) & 1);
                uint32_t r[4];
                ldsm4(r, stage_base + ARR_BYTES + sw_off(row, ch));
                bhf[p*2][0] = r[0]; bhf[p*2][1] = r[1];
                bhf[p*2+1][0] = r[2]; bhf[p*2+1][1] = r[3];
            }
            // A fragments: 4 m-tiles of 16 rows
            #pragma unroll
            for (int mt = 0; mt < 4; mt++) {
                int row = wm + mt * 16 + (lane & 15);
                int ch = ks * 2 + (lane >> 4);
                ldsm4(ahf[mt], stage_base + sw_off(row, ch));
            }
            #pragma unroll
            for (int mt = 0; mt < 4; mt++)
                #pragma unroll
                for (int nt = 0; nt < 8; nt++)
                    mma16816(acc[mt][nt], ahf[mt], bhf[nt]);
        }
    };

    fill(0, 0); CP_COMMIT();
    fill(1, 1); CP_COMMIT();

    for (int t = 0; t < NKT2; t++) {
        if (t + 1 < NKT2) { CP_WAIT(1); } else { CP_WAIT(0); }
        __syncthreads();
        if (t + 2 < NKT2) {
            fill((t + 2) % NST, t + 2);
            CP_COMMIT();
        }
        compute(t % NST);
    }

    // ---- epilogue ----
    #pragma unroll
    for (int mt = 0; mt < 4; mt++) {
        #pragma unroll
        for (int nt = 0; nt < 8; nt++) {
            int r = m0 + wm + mt * 16 + (lane >> 2);
            int c = n0 + wn + nt * 8 + (lane & 3) * 2;
            float2 bv = *(const float2*)&bias[c];
            #pragma unroll
            for (int half = 0; half < 2; half++) {
                int rr = r + half * 8;
                const size_t off = (size_t)rr * DD + c;
                float2 o;
                o.x = acc[mt][nt][half * 2 + 0] + bv.x;
                o.y = acc[mt][nt][half * 2 + 1] + bv.y;
                if (RESID) {
                    float2 qv = *(const float2*)&resid[off];
                    o.x += qv.x; o.y += qv.y;
                }
                *(float2*)&C[off] = o;
                if (EMITH && emit_h)
                    *(__half2*)&qh[off] = __floats2half2_rn(o.x, o.y);
            }
        }
    }
}

// ---------------------------------------------------------------------------
// fp32 -> fp16 convert (hs)
// ---------------------------------------------------------------------------
__global__ __launch_bounds__(256)
void cvt_kernel(const float* __restrict__ x, __half* __restrict__ y)
{
    size_t e = ((size_t)blockIdx.x * 256 + threadIdx.x) * 4;
    float4 v = *(const float4*)(x + e);
    *(__half2*)(y + e)     = __floats2half2_rn(v.x, v.y);
    *(__half2*)(y + e + 2) = __floats2half2_rn(v.z, v.w);
}

// W[K][N] fp32 -> B[N][K] fp16 (transpose + convert)
__global__ __launch_bounds__(256)
void wcvt_kernel(const float* __restrict__ W, __half* __restrict__ Bh)
{
    __shared__ float t[32][33];
    const int tx = threadIdx.x, ty = threadIdx.y;
    const int nx = blockIdx.x * 32, ky = blockIdx.y * 32;
    #pragma unroll
    for (int i = 0; i < 4; i++)
        t[ty + 8 * i][tx] = W[(size_t)(ky + ty + 8 * i) * DD + nx + tx];
    __syncthreads();
    #pragma unroll
    for (int i = 0; i < 4; i++)
        Bh[(size_t)(nx + ty + 8 * i) * DD + ky + tx] = __float2half_rn(t[tx][ty + 8 * i]);
}

// per-batch scaled weight: out[b][n][k] = fp16(W[k][n] * pk[b][k]), grid.z = batch
__global__ __launch_bounds__(256)
void wcvt_scaled_kernel(const float* __restrict__ W, const float* __restrict__ pk,
                        __half* __restrict__ Bh)
{
    __shared__ float t[32][33];
    const int tx = threadIdx.x, ty = threadIdx.y;
    const int nx = blockIdx.x * 32, ky = blockIdx.y * 32;
    const int b = blockIdx.z;
    #pragma unroll
    for (int i = 0; i < 4; i++)
        t[ty + 8 * i][tx] = W[(size_t)(ky + ty + 8 * i) * DD + nx + tx];
    __syncthreads();
    const float s = pk[b * DD + ky + tx];
    const size_t bo = (size_t)b * DD * DD;
    #pragma unroll
    for (int i = 0; i < 4; i++)
        Bh[bo + (size_t)(nx + ty + 8 * i) * DD + ky + tx] =
            __float2half_rn(t[tx][ty + 8 * i] * s);
}

// ---------------------------------------------------------------------------
// qa = q @ Wqa + bqa  (thread per (row, head), 4 acc chains)
// ---------------------------------------------------------------------------
__global__ __launch_bounds__(256)
void qa_kernel(const float* __restrict__ Wqa, const float* __restrict__ bqa)
{
    const int h = threadIdx.x & 15;
    const int r = threadIdx.x >> 4;
    const int row = blockIdx.x * 16 + r;
    const float* qrow = &g_q[(size_t)row * DD];

    float a0 = 0.f, a1 = 0.f, a2 = 0.f, a3 = 0.f;
    #pragma unroll 2
    for (int k = 0; k < DD; k += 16) {
        float4 q0 = *(const float4*)&qrow[k + 0];
        float4 q1 = *(const float4*)&qrow[k + 4];
        float4 q2 = *(const float4*)&qrow[k + 8];
        float4 q3 = *(const float4*)&qrow[k + 12];
        a0 = fmaf(q0.x, Wqa[(k + 0)  * HH + h], a0);
        a0 = fmaf(q0.y, Wqa[(k + 1)  * HH + h], a0);
        a0 = fmaf(q0.z, Wqa[(k + 2)  * HH + h], a0);
        a0 = fmaf(q0.w, Wqa[(k + 3)  * HH + h], a0);
        a1 = fmaf(q1.x, Wqa[(k + 4)  * HH + h], a1);
        a1 = fmaf(q1.y, Wqa[(k + 5)  * HH + h], a1);
        a1 = fmaf(q1.z, Wqa[(k + 6)  * HH + h], a1);
        a1 = fmaf(q1.w, Wqa[(k + 7)  * HH + h], a1);
        a2 = fmaf(q2.x, Wqa[(k + 8)  * HH + h], a2);
        a2 = fmaf(q2.y, Wqa[(k + 9)  * HH + h], a2);
        a2 = fmaf(q2.z, Wqa[(k + 10) * HH + h], a2);
        a2 = fmaf(q2.w, Wqa[(k + 11) * HH + h], a2);
        a3 = fmaf(q3.x, Wqa[(k + 12) * HH + h], a3);
        a3 = fmaf(q3.y, Wqa[(k + 13) * HH + h], a3);
        a3 = fmaf(q3.z, Wqa[(k + 14) * HH + h], a3);
        a3 = fmaf(q3.w, Wqa[(k + 15) * HH + h], a3);
    }
    g_qa[(size_t)row * HH + h] = ((a0 + a1) + (a2 + a3)) + bqa[h];
}

// ---------------------------------------------------------------------------
// pool_q / pool_k (exact best-config forms)
// ---------------------------------------------------------------------------
__global__ __launch_bounds__(256)
void pool_q_kernel(const float* __restrict__ mask)
{
    __shared__ float w[SS];
    __shared__ float red[8];
    __shared__ float part[4][DHH];
    const int b = blockIdx.x / HH, h = blockIdx.x % HH;
    const int tid = threadIdx.x;
    const float scale = 0.125f;

    float lmax = -1e30f;
    for (int s = tid; s < SS; s += 256) {
        float sc = g_qa[((size_t)b * SS + s) * HH + h] * scale + mask[b * SS + s];
        w[s] = sc;
        lmax = fmaxf(lmax, sc);
    }
    #pragma unroll
    for (int o = 16; o; o >>= 1) lmax = fmaxf(lmax, __shfl_xor_sync(0xffffffffu, lmax, o));
    if ((tid & 31) == 0) red[tid >> 5] = lmax;
    __syncthreads();
    float gmax = red[0];
    #pragma unroll
    for (int i = 1; i < 8; i++) gmax = fmaxf(gmax, red[i]);
    __syncthreads();

    float lsum = 0.f;
    for (int s = tid; s < SS; s += 256) { float e = expf(w[s] - gmax); w[s] = e; lsum += e; }
    #pragma unroll
    for (int o = 16; o; o >>= 1) lsum += __shfl_xor_sync(0xffffffffu, lsum, o);
    if ((tid & 31) == 0) red[tid >> 5] = lsum;
    __syncthreads();
    float gsum = 0.f;
    #pragma unroll
    for (int i = 0; i < 8; i++) gsum += red[i];
    const float inv = 1.0f / gsum;

    const int dh = tid & 63, sg = tid >> 6;
    float acc = 0.f;
    for (int s = sg; s < SS; s += 4)
        acc = fmaf(w[s], g_q[((size_t)b * SS + s) * DD + h * DHH + dh], acc);
    part[sg][dh] = acc;
    __syncthreads();
    if (tid < DHH)
        g_pq[b * DD + h * DHH + tid] =
            (part[0][tid] + part[1][tid] + part[2][tid] + part[3][tid]) * inv;
}

__global__ __launch_bounds__(256)
void pool_k_kernel(const float* __restrict__ mask)
{
    __shared__ float w[SS];
    __shared__ float red[8];
    __shared__ float part[4][DHH];
    __shared__ float pq[DHH];
    const int b = blockIdx.x / HH, h = blockIdx.x % HH;
    const int tid = threadIdx.x;
    const int lane = tid & 31, warp = tid >> 5;

    if (tid < DHH) pq[tid] = g_pq[b * DD + h * DHH + tid];
    __syncthreads();

    for (int s = warp; s < SS; s += 8) {
        const float* krow = &g_k[((size_t)b * SS + s) * DD + h * DHH];
        float p = krow[lane] * pq[lane] + krow[lane + 32] * pq[lane + 32];
        #pragma unroll
        for (int o = 16; o; o >>= 1) p += __shfl_xor_sync(0xffffffffu, p, o);
        if (lane == 0) w[s] = p * 0.125f + mask[b * SS + s];
    }
    __syncthreads();

    float lmax = -1e30f;
    for (int s = tid; s < SS; s += 256) lmax = fmaxf(lmax, w[s]);
    #pragma unroll
    for (int o = 16; o; o >>= 1) lmax = fmaxf(lmax, __shfl_xor_sync(0xffffffffu, lmax, o));
    if ((tid & 31) == 0) red[tid >> 5] = lmax;
    __syncthreads();
    float gmax = red[0];
    #pragma unroll
    for (int i = 1; i < 8; i++) gmax = fmaxf(gmax, red[i]);
    __syncthreads();

    float lsum = 0.f;
    for (int s = tid; s < SS; s += 256) { float e = expf(w[s] - gmax); w[s] = e; lsum += e; }
    #pragma unroll
    for (int o = 16; o; o >>= 1) lsum += __shfl_xor_sync(0xffffffffu, lsum, o);
    if ((tid & 31) == 0) red[tid >> 5] = lsum;
    __syncthreads();
    float gsum = 0.f;
    #pragma unroll
    for (int i = 0; i < 8; i++) gsum += red[i];
    const float inv = 1.0f / gsum;

    const int dh = tid & 63, sg = tid >> 6;
    float acc = 0.f;
    for (int s = sg; s < SS; s += 4)
        acc = fmaf(w[s], g_k[((size_t)b * SS + s) * DD + h * DHH + dh], acc);
    part[sg][dh] = acc;
    __syncthreads();
    if (tid < DHH)
        g_pk[b * DD + h * DHH + tid] =
            (part[0][tid] + part[1][tid] + part[2][tid] + part[3][tid]) * inv;
}

// ---------------------------------------------------------------------------
extern "C" void kernel_launch(void* const* d_in, const int* in_sizes, int n_in,
                              void* d_out, int out_size)
{
    const float* hs   = (const float*)d_in[0];
    const float* mask = (const float*)d_in[1];
    const float* Wq   = (const float*)d_in[2];
    const float* bq   = (const float*)d_in[3];
    const float* Wqa  = (const float*)d_in[4];
    const float* bqa  = (const float*)d_in[5];
    const float* Wk   = (const float*)d_in[6];
    const float* bk   = (const float*)d_in[7];
    const float* Wt   = (const float*)d_in[8];
    const float* bt   = (const float*)d_in[9];
    float* out = (float*)d_out;

    float *q, *k, *pk;
    __half *ah, *qh, *wh1, *wh2, *wth8;
    cudaGetSymbolAddress((void**)&q,    g_q);
    cudaGetSymbolAddress((void**)&k,    g_k);
    cudaGetSymbolAddress((void**)&pk,   g_pk);
    cudaGetSymbolAddress((void**)&ah,   g_ah);
    cudaGetSymbolAddress((void**)&qh,   g_qh);
    cudaGetSymbolAddress((void**)&wh1,  g_wh1);
    cudaGetSymbolAddress((void**)&wh2,  g_wh2);
    cudaGetSymbolAddress((void**)&wth8, g_wth8);

    cudaFuncSetAttribute(gemm_mma<false, true, true, false>,
                         cudaFuncAttributeMaxDynamicSharedMemorySize, GEMM_SMEM);
    cudaFuncSetAttribute(gemm_mma<true, false, false, true>,
                         cudaFuncAttributeMaxDynamicSharedMemorySize, GEMM_SMEM);

    const int ncvt = (int)(((size_t)M_TOT * DD / 4) / 256);
    dim3 wgrid(DD / 32, DD / 32), wblk(32, 8);
    dim3 wsgrid(DD / 32, DD / 32, BB);
    dim3 ggrid_dual(16, M_TOT / 128);
    dim3 ggrid(8, M_TOT / 128);

    cvt_kernel<<<ncvt, 256>>>(hs, ah);
    wcvt_kernel<<<wgrid, wblk>>>(Wq, wh1);
    wcvt_kernel<<<wgrid, wblk>>>(Wk, wh2);

    // fused q+k projection; q-half stores fp32 q AND emits fp16 q
    gemm_mma<false, true, true, false><<<ggrid_dual, 128, GEMM_SMEM>>>(
        ah, wh1, wh2, bq, bk, q, k, nullptr, qh);

    qa_kernel<<<M_TOT / 16, 256>>>(Wqa, bqa);
    pool_q_kernel<<<BB * HH, 256>>>(mask);
    pool_k_kernel<<<BB * HH, 256>>>(mask);

    // per-batch scaled transform weights
    wcvt_scaled_kernel<<<wsgrid, wblk>>>(Wt, pk, wth8);

    // out = q @ (diag(pk[b]) Wt) + bt + q
    gemm_mma<true, false, false, true><<<ggrid, 128, GEMM_SMEM>>>(
        qh, wth8, wth8, bt, bt, out, out, q, nullptr);
}